// round 1
// baseline (speedup 1.0000x reference)
#include <cuda_runtime.h>
#include <math.h>
#include <stdint.h>

// Problem constants
#define CL 4
#define CDM 768
#define CDI 1536
#define CDS 16
#define CDR 48
#define CKC 4
#define CV 32000
#define CB 2
#define CS 2048
#define CBS (CB*CS)          // 4096 tokens
#define CDBC 80              // DR + 2*DS

// ---------------- scratch arena (no allocations allowed) ----------------
#define SZ_H   ((size_t)CBS*CDM)      // 3,145,728
#define SZ_XZ  ((size_t)CBS*2*CDI)   // 12,582,912
#define SZ_XC  ((size_t)CBS*CDI)     // 6,291,456
#define SZ_DBC ((size_t)CBS*CDBC)    // 327,680

#define O_H0   ((size_t)0)
#define O_H1   (O_H0 + SZ_H)
#define O_XN0  (O_H1 + SZ_H)
#define O_XN1  (O_XN0 + SZ_H)
#define O_XZ0  (O_XN1 + SZ_H)
#define O_XZ1  (O_XZ0 + SZ_XZ)
#define O_XC0  (O_XZ1 + SZ_XZ)
#define O_XC1  (O_XC0 + SZ_XC)
#define O_DBC0 (O_XC1 + SZ_XC)
#define O_DBC1 (O_DBC0 + SZ_DBC)
#define O_DT0  (O_DBC1 + SZ_DBC)
#define O_DT1  (O_DT0 + SZ_XC)
#define O_Y0   (O_DT1 + SZ_XC)
#define O_Y1   (O_Y0 + SZ_XC)
#define O_COMB (O_Y1 + SZ_XC)
#define O_NLL  (O_COMB + (size_t)CBS*2*CDM)
#define O_VAL  (O_NLL + CBS)
#define ARENA_TOTAL (O_VAL + CBS)

__device__ float g_arena[ARENA_TOTAL];

// ---------------- embedding (with optional time flip for bw) ----------------
__global__ void embed_kernel(const int* __restrict__ ids,
                             const float* __restrict__ emb,
                             float* __restrict__ h, int flip)
{
    size_t idx = (size_t)blockIdx.x * blockDim.x + threadIdx.x;
    if (idx >= (size_t)CBS * CDM) return;
    int r = (int)(idx / CDM);
    int c = (int)(idx % CDM);
    int b = r / CS, t = r % CS;
    int tt = flip ? (CS - 1 - t) : t;
    int id = ids[b * CS + tt];
    h[idx] = emb[(size_t)id * CDM + c];
}

// ---------------- RMSNorm (one block per token) ----------------
__global__ void rms_kernel(const float* __restrict__ x,
                           const float* __restrict__ w,
                           float* __restrict__ out)
{
    int r = blockIdx.x;
    const float* xr = x + (size_t)r * CDM;
    float s = 0.f;
    for (int i = threadIdx.x; i < CDM; i += blockDim.x) { float v = xr[i]; s += v * v; }
    __shared__ float sm[8];
    __shared__ float scale_sh;
    for (int o = 16; o > 0; o >>= 1) s += __shfl_xor_sync(0xffffffffu, s, o);
    if ((threadIdx.x & 31) == 0) sm[threadIdx.x >> 5] = s;
    __syncthreads();
    if (threadIdx.x == 0) {
        float t = 0.f;
        for (int i = 0; i < 8; i++) t += sm[i];
        scale_sh = rsqrtf(t / CDM + 1e-5f);
    }
    __syncthreads();
    float sc = scale_sh;
    for (int i = threadIdx.x; i < CDM; i += blockDim.x)
        out[(size_t)r * CDM + i] = xr[i] * sc * w[i];
}

// ---------------- generic GEMM: C[M,N] (+)= A[M,K(lda)] * B[N,K]^T ----------------
// act: 0 = none, 1 = softplus.  bias: per-column or nullptr.  acc: add into C.
__global__ __launch_bounds__(256)
void gemm_kernel(const float* __restrict__ A, int lda,
                 const float* __restrict__ Bw,
                 float* __restrict__ C,
                 int M, int N, int K,
                 const float* __restrict__ bias,
                 int act, int acc)
{
    __shared__ float As[16][64];
    __shared__ float Bs[16][64];
    int tid = threadIdx.x;
    int tx = tid & 15, ty = tid >> 4;
    int m0 = blockIdx.y * 64;
    int n0 = blockIdx.x * 64;
    int lr = tid >> 2;          // 0..63
    int lc = (tid & 3) << 2;    // 0,4,8,12
    float c[4][4] = {};
    for (int k0 = 0; k0 < K; k0 += 16) {
        float4 av = make_float4(0.f, 0.f, 0.f, 0.f);
        int am = m0 + lr;
        if (am < M) av = *(const float4*)(A + (size_t)am * lda + k0 + lc);
        As[lc + 0][lr] = av.x; As[lc + 1][lr] = av.y;
        As[lc + 2][lr] = av.z; As[lc + 3][lr] = av.w;
        float4 bv = make_float4(0.f, 0.f, 0.f, 0.f);
        int bn = n0 + lr;
        if (bn < N) bv = *(const float4*)(Bw + (size_t)bn * K + k0 + lc);
        Bs[lc + 0][lr] = bv.x; Bs[lc + 1][lr] = bv.y;
        Bs[lc + 2][lr] = bv.z; Bs[lc + 3][lr] = bv.w;
        __syncthreads();
#pragma unroll
        for (int kk = 0; kk < 16; kk++) {
            float4 a = *(const float4*)&As[kk][ty << 2];
            float4 b = *(const float4*)&Bs[kk][tx << 2];
            c[0][0] += a.x * b.x; c[0][1] += a.x * b.y; c[0][2] += a.x * b.z; c[0][3] += a.x * b.w;
            c[1][0] += a.y * b.x; c[1][1] += a.y * b.y; c[1][2] += a.y * b.z; c[1][3] += a.y * b.w;
            c[2][0] += a.z * b.x; c[2][1] += a.z * b.y; c[2][2] += a.z * b.z; c[2][3] += a.z * b.w;
            c[3][0] += a.w * b.x; c[3][1] += a.w * b.y; c[3][2] += a.w * b.z; c[3][3] += a.w * b.w;
        }
        __syncthreads();
    }
#pragma unroll
    for (int i = 0; i < 4; i++) {
        int m = m0 + (ty << 2) + i;
        if (m >= M) continue;
#pragma unroll
        for (int j = 0; j < 4; j++) {
            int n = n0 + (tx << 2) + j;
            if (n >= N) continue;
            float v = c[i][j];
            if (bias) v += bias[n];
            if (act == 1) v = (v > 20.f) ? v : log1pf(expf(v));
            size_t off = (size_t)m * N + n;
            if (acc) v += C[off];
            C[off] = v;
        }
    }
}

// ---------------- causal conv (k=4) + bias + silu ----------------
__global__ void conv_kernel(const float* __restrict__ xz,
                            const float* __restrict__ convw,
                            const float* __restrict__ convb,
                            float* __restrict__ xc)
{
    size_t idx = (size_t)blockIdx.x * blockDim.x + threadIdx.x;
    if (idx >= (size_t)CBS * CDI) return;
    int r = (int)(idx / CDI);
    int d = (int)(idx % CDI);
    int t = r % CS;
    float acc = convb[d];
#pragma unroll
    for (int k = 0; k < CKC; k++) {
        int tt = t - (CKC - 1) + k;
        if (tt >= 0)
            acc += xz[(size_t)(r - (CKC - 1) + k) * (2 * CDI) + d] * convw[d * CKC + k];
    }
    float sg = 1.f / (1.f + expf(-acc));
    xc[idx] = acc * sg;
}

// ---------------- selective scan: 16 lanes per (b,d) channel ----------------
__global__ void scan_kernel(const float* __restrict__ dt,
                            const float* __restrict__ xc,
                            const float* __restrict__ dbc,
                            const float* __restrict__ Alog_l,
                            float* __restrict__ y)
{
    int gid = blockIdx.x * blockDim.x + threadIdx.x;
    int lane = gid & 15;
    int grp = gid >> 4;
    if (grp >= CB * CDI) return;
    int d = grp % CDI;
    int b = grp / CDI;
    float Aval = -expf(Alog_l[d * CDS + lane]);
    float h = 0.f;
    const float* dtp = dt + (size_t)b * CS * CDI + d;
    const float* xp  = xc + (size_t)b * CS * CDI + d;
    const float* bp  = dbc + (size_t)b * CS * CDBC + CDR + lane;
    const float* cp  = dbc + (size_t)b * CS * CDBC + CDR + CDS + lane;
    float* yp        = y + (size_t)b * CS * CDI + d;
    for (int t = 0; t < CS; t++) {
        float dtv = dtp[(size_t)t * CDI];
        float xv  = xp[(size_t)t * CDI];
        float Bv  = bp[(size_t)t * CDBC];
        float Cv  = cp[(size_t)t * CDBC];
        float a = expf(dtv * Aval);
        h = a * h + (dtv * xv) * Bv;
        float contrib = h * Cv;
        contrib += __shfl_xor_sync(0xffffffffu, contrib, 8);
        contrib += __shfl_xor_sync(0xffffffffu, contrib, 4);
        contrib += __shfl_xor_sync(0xffffffffu, contrib, 2);
        contrib += __shfl_xor_sync(0xffffffffu, contrib, 1);
        if (lane == 0) yp[(size_t)t * CDI] = contrib;
    }
}

// ---------------- gate: g = (y + Dp*xc) * silu(z) ----------------
__global__ void gate_kernel(float* __restrict__ y,
                            const float* __restrict__ xc,
                            const float* __restrict__ xz,
                            const float* __restrict__ Dp)
{
    size_t idx = (size_t)blockIdx.x * blockDim.x + threadIdx.x;
    if (idx >= (size_t)CBS * CDI) return;
    int r = (int)(idx / CDI);
    int d = (int)(idx % CDI);
    float z = xz[(size_t)r * (2 * CDI) + CDI + d];
    float sz = z / (1.f + expf(-z));
    y[idx] = (y[idx] + Dp[d] * xc[idx]) * sz;
}

// ---------------- final rms + concat (bw flipped back) ----------------
__global__ void combined_kernel(const float* __restrict__ hf,
                                const float* __restrict__ hb,
                                const float* __restrict__ wf,
                                const float* __restrict__ wb,
                                float* __restrict__ comb)
{
    int r = blockIdx.x;
    int b = r / CS, t = r % CS;
    const float* xf = hf + (size_t)r * CDM;
    const float* xb = hb + ((size_t)b * CS + (CS - 1 - t)) * CDM;
    __shared__ float sm[8];
    __shared__ float sc_sh;

    // forward half
    float s = 0.f;
    for (int i = threadIdx.x; i < CDM; i += blockDim.x) { float v = xf[i]; s += v * v; }
    for (int o = 16; o > 0; o >>= 1) s += __shfl_xor_sync(0xffffffffu, s, o);
    if ((threadIdx.x & 31) == 0) sm[threadIdx.x >> 5] = s;
    __syncthreads();
    if (threadIdx.x == 0) {
        float tt = 0.f; for (int i = 0; i < 8; i++) tt += sm[i];
        sc_sh = rsqrtf(tt / CDM + 1e-5f);
    }
    __syncthreads();
    float sc = sc_sh;
    for (int i = threadIdx.x; i < CDM; i += blockDim.x)
        comb[(size_t)r * (2 * CDM) + i] = xf[i] * sc * wf[i];
    __syncthreads();

    // backward half (flipped)
    s = 0.f;
    for (int i = threadIdx.x; i < CDM; i += blockDim.x) { float v = xb[i]; s += v * v; }
    for (int o = 16; o > 0; o >>= 1) s += __shfl_xor_sync(0xffffffffu, s, o);
    if ((threadIdx.x & 31) == 0) sm[threadIdx.x >> 5] = s;
    __syncthreads();
    if (threadIdx.x == 0) {
        float tt = 0.f; for (int i = 0; i < 8; i++) tt += sm[i];
        sc_sh = rsqrtf(tt / CDM + 1e-5f);
    }
    __syncthreads();
    sc = sc_sh;
    for (int i = threadIdx.x; i < CDM; i += blockDim.x)
        comb[(size_t)r * (2 * CDM) + CDM + i] = xb[i] * sc * wb[i];
}

// ---------------- per-row cross-entropy ----------------
__global__ void loss_row_kernel(const float* __restrict__ logits,
                                const int* __restrict__ labels,
                                float* __restrict__ nll,
                                float* __restrict__ valid)
{
    int r = blockIdx.x;
    const float* row = logits + (size_t)r * CV;
    __shared__ float sm[8];
    __shared__ float red_sh;

    float mx = -3.4e38f;
    for (int i = threadIdx.x; i < CV; i += blockDim.x) mx = fmaxf(mx, row[i]);
    for (int o = 16; o > 0; o >>= 1) mx = fmaxf(mx, __shfl_xor_sync(0xffffffffu, mx, o));
    if ((threadIdx.x & 31) == 0) sm[threadIdx.x >> 5] = mx;
    __syncthreads();
    if (threadIdx.x == 0) {
        float t = sm[0]; for (int i = 1; i < 8; i++) t = fmaxf(t, sm[i]);
        red_sh = t;
    }
    __syncthreads();
    mx = red_sh;

    float s = 0.f;
    for (int i = threadIdx.x; i < CV; i += blockDim.x) s += expf(row[i] - mx);
    for (int o = 16; o > 0; o >>= 1) s += __shfl_xor_sync(0xffffffffu, s, o);
    if ((threadIdx.x & 31) == 0) sm[threadIdx.x >> 5] = s;
    __syncthreads();
    if (threadIdx.x == 0) {
        float t = 0.f; for (int i = 0; i < 8; i++) t += sm[i];
        int lab = labels[r];
        if (lab == -100) { nll[r] = 0.f; valid[r] = 0.f; }
        else {
            nll[r] = -(row[lab] - mx - logf(t));
            valid[r] = 1.f;
        }
    }
}

__global__ void loss_final_kernel(const float* __restrict__ nll,
                                  const float* __restrict__ valid,
                                  float* __restrict__ out)
{
    __shared__ float sm[8], sc[8];
    float s = 0.f, c = 0.f;
    for (int i = threadIdx.x; i < CBS; i += blockDim.x) { s += nll[i]; c += valid[i]; }
    for (int o = 16; o > 0; o >>= 1) {
        s += __shfl_xor_sync(0xffffffffu, s, o);
        c += __shfl_xor_sync(0xffffffffu, c, o);
    }
    if ((threadIdx.x & 31) == 0) { sm[threadIdx.x >> 5] = s; sc[threadIdx.x >> 5] = c; }
    __syncthreads();
    if (threadIdx.x == 0) {
        float ts = 0.f, tc = 0.f;
        for (int i = 0; i < 8; i++) { ts += sm[i]; tc += sc[i]; }
        out[0] = ts / fmaxf(tc, 1.f);
    }
}

// ---------------- host orchestration ----------------
extern "C" void kernel_launch(void* const* d_in, const int* in_sizes, int n_in,
                              void* d_out, int out_size)
{
    const int* ids    = (const int*)d_in[0];
    const int* labels = (const int*)d_in[1];
    const float* P[27];
    for (int i = 2; i < 27; i++) P[i] = (const float*)d_in[i];

    // param index helpers: fw base 2, bw base 14
    const float* emb[2]   = { P[2],  P[14] };
    const float* norm[2]  = { P[3],  P[15] };
    const float* inw[2]   = { P[4],  P[16] };
    const float* convw[2] = { P[5],  P[17] };
    const float* convb[2] = { P[6],  P[18] };
    const float* xpw[2]   = { P[7],  P[19] };
    const float* dtw[2]   = { P[8],  P[20] };
    const float* dtb[2]   = { P[9],  P[21] };
    const float* Alog[2]  = { P[10], P[22] };
    const float* Dp[2]    = { P[11], P[23] };
    const float* outw[2]  = { P[12], P[24] };
    const float* fnorm[2] = { P[13], P[25] };
    const float* lm_w     = P[26];

    float* arena = nullptr;
    cudaGetSymbolAddress((void**)&arena, g_arena);

    float* hB[2]   = { arena + O_H0,   arena + O_H1 };
    float* xnB[2]  = { arena + O_XN0,  arena + O_XN1 };
    float* xzB[2]  = { arena + O_XZ0,  arena + O_XZ1 };
    float* xcB[2]  = { arena + O_XC0,  arena + O_XC1 };
    float* dbcB[2] = { arena + O_DBC0, arena + O_DBC1 };
    float* dtB[2]  = { arena + O_DT0,  arena + O_DT1 };
    float* yB[2]   = { arena + O_Y0,   arena + O_Y1 };
    float* comb    = arena + O_COMB;
    float* nllb    = arena + O_NLL;
    float* valb    = arena + O_VAL;
    float* logits  = (float*)d_out;

    const int EL_THREADS = 256;
    int grid_hdm = (int)(((size_t)CBS * CDM + EL_THREADS - 1) / EL_THREADS);
    int grid_hdi = (int)(((size_t)CBS * CDI + EL_THREADS - 1) / EL_THREADS);

    // embeddings (bw gets flipped time)
    embed_kernel<<<grid_hdm, EL_THREADS>>>(ids, emb[0], hB[0], 0);
    embed_kernel<<<grid_hdm, EL_THREADS>>>(ids, emb[1], hB[1], 1);

    for (int l = 0; l < CL; l++) {
        for (int dir = 0; dir < 2; dir++) {
            // rms
            rms_kernel<<<CBS, 256>>>(hB[dir], norm[dir] + (size_t)l * CDM, xnB[dir]);
            // xz = xn @ inw^T : [4096,768] x [3072,768]^T
            gemm_kernel<<<dim3((2 * CDI) / 64, CBS / 64), 256>>>(
                xnB[dir], CDM, inw[dir] + (size_t)l * 2 * CDI * CDM,
                xzB[dir], CBS, 2 * CDI, CDM, nullptr, 0, 0);
            // conv + silu
            conv_kernel<<<grid_hdi, EL_THREADS>>>(
                xzB[dir], convw[dir] + (size_t)l * CDI * CKC,
                convb[dir] + (size_t)l * CDI, xcB[dir]);
            // dbc = xc @ xpw^T : [4096,1536] x [80,1536]^T
            gemm_kernel<<<dim3((CDBC + 63) / 64, CBS / 64), 256>>>(
                xcB[dir], CDI, xpw[dir] + (size_t)l * CDBC * CDI,
                dbcB[dir], CBS, CDBC, CDI, nullptr, 0, 0);
            // dt = softplus(dbc[:, :48] @ dtw^T + dtb) : lda = 80, K = 48
            gemm_kernel<<<dim3(CDI / 64, CBS / 64), 256>>>(
                dbcB[dir], CDBC, dtw[dir] + (size_t)l * CDI * CDR,
                dtB[dir], CBS, CDI, CDR, dtb[dir] + (size_t)l * CDI, 1, 0);
            // selective scan
            scan_kernel<<<(CB * CDI * 16 + 255) / 256, 256>>>(
                dtB[dir], xcB[dir], dbcB[dir],
                Alog[dir] + (size_t)l * CDI * CDS, yB[dir]);
            // gate
            gate_kernel<<<grid_hdi, EL_THREADS>>>(
                yB[dir], xcB[dir], xzB[dir], Dp[dir] + (size_t)l * CDI);
            // h += g @ outw^T : [4096,1536] x [768,1536]^T, accumulate
            gemm_kernel<<<dim3(CDM / 64, CBS / 64), 256>>>(
                yB[dir], CDI, outw[dir] + (size_t)l * CDM * CDI,
                hB[dir], CBS, CDM, CDI, nullptr, 0, 1);
        }
    }

    // final rms + concat (bw flipped back)
    combined_kernel<<<CBS, 256>>>(hB[0], hB[1], fnorm[0], fnorm[1], comb);

    // LM head: logits = comb @ lm_w^T : [4096,1536] x [32000,1536]^T
    gemm_kernel<<<dim3(CV / 64, CBS / 64), 256>>>(
        comb, 2 * CDM, lm_w, logits, CBS, CV, 2 * CDM, nullptr, 0, 0);

    // loss
    loss_row_kernel<<<CBS, 256>>>(logits, labels, nllb, valb);
    loss_final_kernel<<<1, 256>>>(nllb, valb, logits + (out_size - 1));
}

// round 2
// speedup vs baseline: 1.3225x; 1.3225x over previous
#include <cuda_runtime.h>
#include <math.h>
#include <stdint.h>

// Problem constants
#define CL 4
#define CDM 768
#define CDI 1536
#define CDS 16
#define CDR 48
#define CKC 4
#define CV 32000
#define CB 2
#define CS 2048
#define CBS (CB*CS)          // 4096 tokens
#define CDBC 80              // DR + 2*DS

// ---------------- scratch arena (no allocations allowed) ----------------
#define SZ_H   ((size_t)CBS*CDM)
#define SZ_XZ  ((size_t)CBS*2*CDI)
#define SZ_XC  ((size_t)CBS*CDI)
#define SZ_DBC ((size_t)CBS*CDBC)

#define O_H0   ((size_t)0)
#define O_H1   (O_H0 + SZ_H)
#define O_XN0  (O_H1 + SZ_H)
#define O_XN1  (O_XN0 + SZ_H)
#define O_XZ0  (O_XN1 + SZ_H)
#define O_XZ1  (O_XZ0 + SZ_XZ)
#define O_XC0  (O_XZ1 + SZ_XZ)
#define O_XC1  (O_XC0 + SZ_XC)
#define O_DBC0 (O_XC1 + SZ_XC)
#define O_DBC1 (O_DBC0 + SZ_DBC)
#define O_DT0  (O_DBC1 + SZ_DBC)
#define O_DT1  (O_DT0 + SZ_XC)
#define O_Y0   (O_DT1 + SZ_XC)
#define O_Y1   (O_Y0 + SZ_XC)
#define O_COMB (O_Y1 + SZ_XC)
#define O_NLL  (O_COMB + (size_t)CBS*2*CDM)
#define O_VAL  (O_NLL + CBS)
#define ARENA_TOTAL (O_VAL + CBS)

__device__ float g_arena[ARENA_TOTAL];

// ---------------- PTX helpers ----------------
__device__ __forceinline__ uint32_t smem_u32(const void* p) {
    uint32_t a;
    asm("{ .reg .u64 t; cvta.to.shared.u64 t, %1; cvt.u32.u64 %0, t; }"
        : "=r"(a) : "l"(p));
    return a;
}

__device__ __forceinline__ float to_tf32(float x) {
    float r;
    asm("cvt.rna.tf32.f32 %0, %1;" : "=f"(r) : "f"(x));
    return r;
}

__device__ __forceinline__ void tf32_split(float x, uint32_t& hi, uint32_t& lo) {
    float h = to_tf32(x);
    hi = __float_as_uint(h);
    lo = __float_as_uint(to_tf32(x - h));
}

#define CP_ASYNC16(dst_u32, src_ptr, sz) \
    asm volatile("cp.async.ca.shared.global [%0], [%1], 16, %2;" \
                 :: "r"(dst_u32), "l"(src_ptr), "r"(sz))
#define CP_COMMIT() asm volatile("cp.async.commit_group;")
#define CP_WAIT(n)  asm volatile("cp.async.wait_group %0;" :: "n"(n))

__device__ __forceinline__ void mma_tf32(float* d, const uint32_t* a, const uint32_t* b) {
    asm volatile(
        "mma.sync.aligned.m16n8k8.row.col.f32.tf32.tf32.f32 "
        "{%0,%1,%2,%3}, {%4,%5,%6,%7}, {%8,%9}, {%0,%1,%2,%3};"
        : "+f"(d[0]), "+f"(d[1]), "+f"(d[2]), "+f"(d[3])
        : "r"(a[0]), "r"(a[1]), "r"(a[2]), "r"(a[3]), "r"(b[0]), "r"(b[1]));
}

// ---------------- tensor-core GEMM (3xTF32): C[M,N] (+)= A[M,K(lda)] * B[N,K]^T
// M must be a multiple of 128; K a multiple of 16; N arbitrary.
#define BM 128
#define BN 128
#define BKK 16
#define APITCH 20   // floats; 20g+tg mod 32 hits 32 distinct banks -> conflict-free

__global__ __launch_bounds__(256)
void gemm_tc(const float* __restrict__ A, int lda,
             const float* __restrict__ Bw,
             float* __restrict__ C,
             int M, int N, int K,
             const float* __restrict__ bias, int act, int acc)
{
    __shared__ float As[2][BM * APITCH];
    __shared__ float Bs[2][BN * APITCH];

    const int tid = threadIdx.x;
    const int wid = tid >> 5, lane = tid & 31;
    const int g = lane >> 2, tg = lane & 3;
    const int warp_m = (wid & 1) * 64;
    const int warp_n = (wid >> 1) * 32;
    const int m0 = blockIdx.y * BM;
    const int n0 = blockIdx.x * BN;

    float accr[4][4][4];
#pragma unroll
    for (int i = 0; i < 4; i++)
#pragma unroll
        for (int j = 0; j < 4; j++)
#pragma unroll
            for (int r = 0; r < 4; r++) accr[i][j][r] = 0.f;

    const uint32_t sA[2] = { smem_u32(As[0]), smem_u32(As[1]) };
    const uint32_t sB[2] = { smem_u32(Bs[0]), smem_u32(Bs[1]) };

    const int nIter = K / BKK;

    // per-thread staging coords: 2 chunks of 16B each for A and B
    const int cm0 = (tid * 2) >> 2;            // row for chunk 0
    const int ck0 = ((tid * 2) & 3) * 4;       // k-offset for chunk 0
    const int cm1 = (tid * 2 + 1) >> 2;
    const int ck1 = ((tid * 2 + 1) & 3) * 4;

#define PREFETCH(it, buf) do {                                                  \
    int k0p = (it) * BKK;                                                       \
    const float* as0 = A + (size_t)(m0 + cm0) * lda + k0p + ck0;                \
    const float* as1 = A + (size_t)(m0 + cm1) * lda + k0p + ck1;                \
    CP_ASYNC16(sA[buf] + (uint32_t)(cm0 * APITCH + ck0) * 4, as0, 16);          \
    CP_ASYNC16(sA[buf] + (uint32_t)(cm1 * APITCH + ck1) * 4, as1, 16);          \
    int bok0 = (n0 + cm0) < N ? 16 : 0;                                         \
    int bok1 = (n0 + cm1) < N ? 16 : 0;                                         \
    const float* bs0 = bok0 ? Bw + (size_t)(n0 + cm0) * K + k0p + ck0 : Bw;     \
    const float* bs1 = bok1 ? Bw + (size_t)(n0 + cm1) * K + k0p + ck1 : Bw;     \
    CP_ASYNC16(sB[buf] + (uint32_t)(cm0 * APITCH + ck0) * 4, bs0, bok0);        \
    CP_ASYNC16(sB[buf] + (uint32_t)(cm1 * APITCH + ck1) * 4, bs1, bok1);        \
    CP_COMMIT();                                                                \
} while (0)

    PREFETCH(0, 0);

    int buf = 0;
    for (int it = 0; it < nIter; it++) {
        if (it + 1 < nIter) {
            PREFETCH(it + 1, buf ^ 1);
            CP_WAIT(1);
        } else {
            CP_WAIT(0);
        }
        __syncthreads();

        const float* Asb = As[buf];
        const float* Bsb = Bs[buf];
#pragma unroll
        for (int ks = 0; ks < BKK; ks += 8) {
            uint32_t ahi[4][4], alo[4][4], bhi[4][2], blo[4][2];
#pragma unroll
            for (int mt = 0; mt < 4; mt++) {
                int row = warp_m + mt * 16;
                float a0 = Asb[(row + g) * APITCH + ks + tg];
                float a1 = Asb[(row + g + 8) * APITCH + ks + tg];
                float a2 = Asb[(row + g) * APITCH + ks + tg + 4];
                float a3 = Asb[(row + g + 8) * APITCH + ks + tg + 4];
                tf32_split(a0, ahi[mt][0], alo[mt][0]);
                tf32_split(a1, ahi[mt][1], alo[mt][1]);
                tf32_split(a2, ahi[mt][2], alo[mt][2]);
                tf32_split(a3, ahi[mt][3], alo[mt][3]);
            }
#pragma unroll
            for (int nt = 0; nt < 4; nt++) {
                int col = warp_n + nt * 8;
                float b0 = Bsb[(col + g) * APITCH + ks + tg];
                float b1 = Bsb[(col + g) * APITCH + ks + tg + 4];
                tf32_split(b0, bhi[nt][0], blo[nt][0]);
                tf32_split(b1, bhi[nt][1], blo[nt][1]);
            }
#pragma unroll
            for (int mt = 0; mt < 4; mt++)
#pragma unroll
                for (int nt = 0; nt < 4; nt++) {
                    mma_tf32(accr[mt][nt], ahi[mt], bhi[nt]);
                    mma_tf32(accr[mt][nt], ahi[mt], blo[nt]);
                    mma_tf32(accr[mt][nt], alo[mt], bhi[nt]);
                }
        }
        __syncthreads();
        buf ^= 1;
    }

    // epilogue
#pragma unroll
    for (int mt = 0; mt < 4; mt++) {
        int row0 = m0 + warp_m + mt * 16 + g;
#pragma unroll
        for (int nt = 0; nt < 4; nt++) {
            int col0 = n0 + warp_n + nt * 8 + tg * 2;
#pragma unroll
            for (int half = 0; half < 2; half++) {
                int m = row0 + half * 8;
#pragma unroll
                for (int j = 0; j < 2; j++) {
                    int n = col0 + j;
                    if (n < N) {
                        float v = accr[mt][nt][half * 2 + j];
                        if (bias) v += bias[n];
                        if (act == 1) v = (v > 20.f) ? v : log1pf(expf(v));
                        size_t off = (size_t)m * N + n;
                        if (acc) v += C[off];
                        C[off] = v;
                    }
                }
            }
        }
    }
}

// ---------------- embedding (with optional time flip for bw) ----------------
__global__ void embed_kernel(const int* __restrict__ ids,
                             const float* __restrict__ emb,
                             float* __restrict__ h, int flip)
{
    size_t idx = (size_t)blockIdx.x * blockDim.x + threadIdx.x;
    if (idx >= (size_t)CBS * CDM) return;
    int r = (int)(idx / CDM);
    int c = (int)(idx % CDM);
    int b = r / CS, t = r % CS;
    int tt = flip ? (CS - 1 - t) : t;
    int id = ids[b * CS + tt];
    h[idx] = emb[(size_t)id * CDM + c];
}

// ---------------- RMSNorm (one block per token) ----------------
__global__ void rms_kernel(const float* __restrict__ x,
                           const float* __restrict__ w,
                           float* __restrict__ out)
{
    int r = blockIdx.x;
    const float* xr = x + (size_t)r * CDM;
    float s = 0.f;
    for (int i = threadIdx.x; i < CDM; i += blockDim.x) { float v = xr[i]; s += v * v; }
    __shared__ float sm[8];
    __shared__ float scale_sh;
    for (int o = 16; o > 0; o >>= 1) s += __shfl_xor_sync(0xffffffffu, s, o);
    if ((threadIdx.x & 31) == 0) sm[threadIdx.x >> 5] = s;
    __syncthreads();
    if (threadIdx.x == 0) {
        float t = 0.f;
        for (int i = 0; i < 8; i++) t += sm[i];
        scale_sh = rsqrtf(t / CDM + 1e-5f);
    }
    __syncthreads();
    float sc = scale_sh;
    for (int i = threadIdx.x; i < CDM; i += blockDim.x)
        out[(size_t)r * CDM + i] = xr[i] * sc * w[i];
}

// ---------------- causal conv (k=4) + bias + silu ----------------
__global__ void conv_kernel(const float* __restrict__ xz,
                            const float* __restrict__ convw,
                            const float* __restrict__ convb,
                            float* __restrict__ xc)
{
    size_t idx = (size_t)blockIdx.x * blockDim.x + threadIdx.x;
    if (idx >= (size_t)CBS * CDI) return;
    int r = (int)(idx / CDI);
    int d = (int)(idx % CDI);
    int t = r % CS;
    float acc = convb[d];
#pragma unroll
    for (int k = 0; k < CKC; k++) {
        int tt = t - (CKC - 1) + k;
        if (tt >= 0)
            acc += xz[(size_t)(r - (CKC - 1) + k) * (2 * CDI) + d] * convw[d * CKC + k];
    }
    float sg = 1.f / (1.f + expf(-acc));
    xc[idx] = acc * sg;
}

// ---------------- selective scan: 16 lanes per (b,d) channel ----------------
__global__ void scan_kernel(const float* __restrict__ dt,
                            const float* __restrict__ xc,
                            const float* __restrict__ dbc,
                            const float* __restrict__ Alog_l,
                            float* __restrict__ y)
{
    int gid = blockIdx.x * blockDim.x + threadIdx.x;
    int lane = gid & 15;
    int grp = gid >> 4;
    if (grp >= CB * CDI) return;
    int d = grp % CDI;
    int b = grp / CDI;
    float Aval = -expf(Alog_l[d * CDS + lane]);
    float h = 0.f;
    const float* dtp = dt + (size_t)b * CS * CDI + d;
    const float* xp  = xc + (size_t)b * CS * CDI + d;
    const float* bp  = dbc + (size_t)b * CS * CDBC + CDR + lane;
    const float* cp  = dbc + (size_t)b * CS * CDBC + CDR + CDS + lane;
    float* yp        = y + (size_t)b * CS * CDI + d;
    for (int t = 0; t < CS; t++) {
        float dtv = dtp[(size_t)t * CDI];
        float xv  = xp[(size_t)t * CDI];
        float Bv  = bp[(size_t)t * CDBC];
        float Cv  = cp[(size_t)t * CDBC];
        float a = expf(dtv * Aval);
        h = a * h + (dtv * xv) * Bv;
        float contrib = h * Cv;
        contrib += __shfl_xor_sync(0xffffffffu, contrib, 8);
        contrib += __shfl_xor_sync(0xffffffffu, contrib, 4);
        contrib += __shfl_xor_sync(0xffffffffu, contrib, 2);
        contrib += __shfl_xor_sync(0xffffffffu, contrib, 1);
        if (lane == 0) yp[(size_t)t * CDI] = contrib;
    }
}

// ---------------- gate: g = (y + Dp*xc) * silu(z) ----------------
__global__ void gate_kernel(float* __restrict__ y,
                            const float* __restrict__ xc,
                            const float* __restrict__ xz,
                            const float* __restrict__ Dp)
{
    size_t idx = (size_t)blockIdx.x * blockDim.x + threadIdx.x;
    if (idx >= (size_t)CBS * CDI) return;
    int r = (int)(idx / CDI);
    int d = (int)(idx % CDI);
    float z = xz[(size_t)r * (2 * CDI) + CDI + d];
    float sz = z / (1.f + expf(-z));
    y[idx] = (y[idx] + Dp[d] * xc[idx]) * sz;
}

// ---------------- final rms + concat (bw flipped back) ----------------
__global__ void combined_kernel(const float* __restrict__ hf,
                                const float* __restrict__ hb,
                                const float* __restrict__ wf,
                                const float* __restrict__ wb,
                                float* __restrict__ comb)
{
    int r = blockIdx.x;
    int b = r / CS, t = r % CS;
    const float* xf = hf + (size_t)r * CDM;
    const float* xb = hb + ((size_t)b * CS + (CS - 1 - t)) * CDM;
    __shared__ float sm[8];
    __shared__ float sc_sh;

    float s = 0.f;
    for (int i = threadIdx.x; i < CDM; i += blockDim.x) { float v = xf[i]; s += v * v; }
    for (int o = 16; o > 0; o >>= 1) s += __shfl_xor_sync(0xffffffffu, s, o);
    if ((threadIdx.x & 31) == 0) sm[threadIdx.x >> 5] = s;
    __syncthreads();
    if (threadIdx.x == 0) {
        float tt = 0.f; for (int i = 0; i < 8; i++) tt += sm[i];
        sc_sh = rsqrtf(tt / CDM + 1e-5f);
    }
    __syncthreads();
    float sc = sc_sh;
    for (int i = threadIdx.x; i < CDM; i += blockDim.x)
        comb[(size_t)r * (2 * CDM) + i] = xf[i] * sc * wf[i];
    __syncthreads();

    s = 0.f;
    for (int i = threadIdx.x; i < CDM; i += blockDim.x) { float v = xb[i]; s += v * v; }
    for (int o = 16; o > 0; o >>= 1) s += __shfl_xor_sync(0xffffffffu, s, o);
    if ((threadIdx.x & 31) == 0) sm[threadIdx.x >> 5] = s;
    __syncthreads();
    if (threadIdx.x == 0) {
        float tt = 0.f; for (int i = 0; i < 8; i++) tt += sm[i];
        sc_sh = rsqrtf(tt / CDM + 1e-5f);
    }
    __syncthreads();
    sc = sc_sh;
    for (int i = threadIdx.x; i < CDM; i += blockDim.x)
        comb[(size_t)r * (2 * CDM) + CDM + i] = xb[i] * sc * wb[i];
}

// ---------------- per-row cross-entropy ----------------
__global__ void loss_row_kernel(const float* __restrict__ logits,
                                const int* __restrict__ labels,
                                float* __restrict__ nll,
                                float* __restrict__ valid)
{
    int r = blockIdx.x;
    const float* row = logits + (size_t)r * CV;
    __shared__ float sm[8];
    __shared__ float red_sh;

    float mx = -3.4e38f;
    for (int i = threadIdx.x; i < CV; i += blockDim.x) mx = fmaxf(mx, row[i]);
    for (int o = 16; o > 0; o >>= 1) mx = fmaxf(mx, __shfl_xor_sync(0xffffffffu, mx, o));
    if ((threadIdx.x & 31) == 0) sm[threadIdx.x >> 5] = mx;
    __syncthreads();
    if (threadIdx.x == 0) {
        float t = sm[0]; for (int i = 1; i < 8; i++) t = fmaxf(t, sm[i]);
        red_sh = t;
    }
    __syncthreads();
    mx = red_sh;

    float s = 0.f;
    for (int i = threadIdx.x; i < CV; i += blockDim.x) s += expf(row[i] - mx);
    for (int o = 16; o > 0; o >>= 1) s += __shfl_xor_sync(0xffffffffu, s, o);
    if ((threadIdx.x & 31) == 0) sm[threadIdx.x >> 5] = s;
    __syncthreads();
    if (threadIdx.x == 0) {
        float t = 0.f; for (int i = 0; i < 8; i++) t += sm[i];
        int lab = labels[r];
        if (lab == -100) { nll[r] = 0.f; valid[r] = 0.f; }
        else {
            nll[r] = -(row[lab] - mx - logf(t));
            valid[r] = 1.f;
        }
    }
}

__global__ void loss_final_kernel(const float* __restrict__ nll,
                                  const float* __restrict__ valid,
                                  float* __restrict__ out)
{
    __shared__ float sm[8], sc[8];
    float s = 0.f, c = 0.f;
    for (int i = threadIdx.x; i < CBS; i += blockDim.x) { s += nll[i]; c += valid[i]; }
    for (int o = 16; o > 0; o >>= 1) {
        s += __shfl_xor_sync(0xffffffffu, s, o);
        c += __shfl_xor_sync(0xffffffffu, c, o);
    }
    if ((threadIdx.x & 31) == 0) { sm[threadIdx.x >> 5] = s; sc[threadIdx.x >> 5] = c; }
    __syncthreads();
    if (threadIdx.x == 0) {
        float ts = 0.f, tc = 0.f;
        for (int i = 0; i < 8; i++) { ts += sm[i]; tc += sc[i]; }
        out[0] = ts / fmaxf(tc, 1.f);
    }
}

// ---------------- host orchestration ----------------
extern "C" void kernel_launch(void* const* d_in, const int* in_sizes, int n_in,
                              void* d_out, int out_size)
{
    const int* ids    = (const int*)d_in[0];
    const int* labels = (const int*)d_in[1];
    const float* P[27];
    for (int i = 2; i < 27; i++) P[i] = (const float*)d_in[i];

    const float* emb[2]   = { P[2],  P[14] };
    const float* norm[2]  = { P[3],  P[15] };
    const float* inw[2]   = { P[4],  P[16] };
    const float* convw[2] = { P[5],  P[17] };
    const float* convb[2] = { P[6],  P[18] };
    const float* xpw[2]   = { P[7],  P[19] };
    const float* dtw[2]   = { P[8],  P[20] };
    const float* dtb[2]   = { P[9],  P[21] };
    const float* Alog[2]  = { P[10], P[22] };
    const float* Dp[2]    = { P[11], P[23] };
    const float* outw[2]  = { P[12], P[24] };
    const float* fnorm[2] = { P[13], P[25] };
    const float* lm_w     = P[26];

    float* arena = nullptr;
    cudaGetSymbolAddress((void**)&arena, g_arena);

    float* hB[2]   = { arena + O_H0,   arena + O_H1 };
    float* xnB[2]  = { arena + O_XN0,  arena + O_XN1 };
    float* xzB[2]  = { arena + O_XZ0,  arena + O_XZ1 };
    float* xcB[2]  = { arena + O_XC0,  arena + O_XC1 };
    float* dbcB[2] = { arena + O_DBC0, arena + O_DBC1 };
    float* dtB[2]  = { arena + O_DT0,  arena + O_DT1 };
    float* yB[2]   = { arena + O_Y0,   arena + O_Y1 };
    float* comb    = arena + O_COMB;
    float* nllb    = arena + O_NLL;
    float* valb    = arena + O_VAL;
    float* logits  = (float*)d_out;

    const int EL_THREADS = 256;
    int grid_hdm = (int)(((size_t)CBS * CDM + EL_THREADS - 1) / EL_THREADS);
    int grid_hdi = (int)(((size_t)CBS * CDI + EL_THREADS - 1) / EL_THREADS);

    embed_kernel<<<grid_hdm, EL_THREADS>>>(ids, emb[0], hB[0], 0);
    embed_kernel<<<grid_hdm, EL_THREADS>>>(ids, emb[1], hB[1], 1);

    for (int l = 0; l < CL; l++) {
        for (int dir = 0; dir < 2; dir++) {
            rms_kernel<<<CBS, 256>>>(hB[dir], norm[dir] + (size_t)l * CDM, xnB[dir]);
            // xz = xn @ inw^T : [4096,768] x [3072,768]^T
            gemm_tc<<<dim3((2 * CDI) / BN, CBS / BM), 256>>>(
                xnB[dir], CDM, inw[dir] + (size_t)l * 2 * CDI * CDM,
                xzB[dir], CBS, 2 * CDI, CDM, nullptr, 0, 0);
            conv_kernel<<<grid_hdi, EL_THREADS>>>(
                xzB[dir], convw[dir] + (size_t)l * CDI * CKC,
                convb[dir] + (size_t)l * CDI, xcB[dir]);
            // dbc = xc @ xpw^T : [4096,1536] x [80,1536]^T
            gemm_tc<<<dim3((CDBC + BN - 1) / BN, CBS / BM), 256>>>(
                xcB[dir], CDI, xpw[dir] + (size_t)l * CDBC * CDI,
                dbcB[dir], CBS, CDBC, CDI, nullptr, 0, 0);
            // dt = softplus(dbc[:, :48] @ dtw^T + dtb)
            gemm_tc<<<dim3(CDI / BN, CBS / BM), 256>>>(
                dbcB[dir], CDBC, dtw[dir] + (size_t)l * CDI * CDR,
                dtB[dir], CBS, CDI, CDR, dtb[dir] + (size_t)l * CDI, 1, 0);
            scan_kernel<<<(CB * CDI * 16 + 255) / 256, 256>>>(
                dtB[dir], xcB[dir], dbcB[dir],
                Alog[dir] + (size_t)l * CDI * CDS, yB[dir]);
            gate_kernel<<<grid_hdi, EL_THREADS>>>(
                yB[dir], xcB[dir], xzB[dir], Dp[dir] + (size_t)l * CDI);
            // h += g @ outw^T : [4096,1536] x [768,1536]^T
            gemm_tc<<<dim3(CDM / BN, CBS / BM), 256>>>(
                yB[dir], CDI, outw[dir] + (size_t)l * CDM * CDI,
                hB[dir], CBS, CDM, CDI, nullptr, 0, 1);
        }
    }

    combined_kernel<<<CBS, 256>>>(hB[0], hB[1], fnorm[0], fnorm[1], comb);

    // LM head: logits = comb @ lm_w^T : [4096,1536] x [32000,1536]^T
    gemm_tc<<<dim3(CV / BN, CBS / BM), 256>>>(
        comb, 2 * CDM, lm_w, logits, CBS, CV, 2 * CDM, nullptr, 0, 0);

    loss_row_kernel<<<CBS, 256>>>(logits, labels, nllb, valb);
    loss_final_kernel<<<1, 256>>>(nllb, valb, logits + (out_size - 1));
}